// round 10
// baseline (speedup 1.0000x reference)
#include <cuda_runtime.h>

// Problem constants (SUBDIVISIONS=7, BATCH=16)
#define BATCH 16
#define YDIM  640
#define XDIM  256
#define BH    128            // YDIM/5
#define YX    (YDIM*XDIM)    // 163840
#define NV    (YX + 2)       // 163842 vertices
#define BPT   2              // batches per thread in the fused loss kernel
#define TPB   256            // k_loss threads per block
#define HALO  258            // covers grid-neighbor offsets +-1, +-X, +-(X+1)
#define SPAN  (TPB + 2*HALO) // 772 staged vertices per block

// Scratch (static __device__ — no allocation allowed)
__device__ float4 g_v4[BATCH * NV];   // padded xyz_ per batch (~42 MB)
__device__ int    g_cnt[NV];          // per-vertex ring fill counters
__device__ int2   g_ring[NV * 6];     // per-vertex opposite-edge pairs (a,b)
__device__ int4   g_nbr[NV * 2];      // ring-ordered neighbors: [n0..n5, cnt, _]
__device__ double g_acc;              // fused loss accumulator
__device__ unsigned int g_done;       // ticket counter for fused finalization

// ---------------------------------------------------------------------------
// K0: zero counters + accumulators (head of the side-stream topology chain)
// ---------------------------------------------------------------------------
__global__ void k_zero() {
    int i = blockIdx.x * blockDim.x + threadIdx.x;
    if (i < NV) g_cnt[i] = 0;
    if (i == 0) { g_acc = 0.0; g_done = 0u; }
}

// ---------------------------------------------------------------------------
// K1: build v = [grid verts ; top pole ; bottom pole] as float4 (w unused).
// inputs layout: (B, 3, Y, X) row-major
// ---------------------------------------------------------------------------
__global__ void k_build_v(const float* __restrict__ inp) {
    int vtx = blockIdx.x * blockDim.x + threadIdx.x;
    int b   = blockIdx.y;
    if (vtx > YX + 1) return;
    const float* base = inp + (size_t)b * 3 * YX;
    float4 o;
    o.w = 0.0f;
    if (vtx < YX) {
        o.x = base[vtx];
        o.y = base[YX + vtx];
        o.z = base[2 * YX + vtx];
    } else if (vtx == YX) {
        float s[3];
        #pragma unroll
        for (int c = 0; c < 3; c++) {
            s[c] = 0.0f;
            #pragma unroll
            for (int i = 0; i < 5; i++) s[c] += base[c * YX + (i * BH) * XDIM];
            s[c] *= 0.2f;
        }
        o.x = s[0]; o.y = s[1]; o.z = s[2];
    } else {
        float s[3];
        #pragma unroll
        for (int c = 0; c < 3; c++) {
            s[c] = 0.0f;
            #pragma unroll
            for (int i = 1; i <= 5; i++)
                s[c] += base[c * YX + (i * BH - 1) * XDIM + (XDIM - 1)];
            s[c] *= 0.2f;
        }
        o.x = s[0]; o.y = s[1]; o.z = s[2];
    }
    g_v4[(size_t)b * NV + vtx] = o;
}

// ---------------------------------------------------------------------------
// K2: collect per-vertex opposite-edge pairs from faces (batch-independent).
// ---------------------------------------------------------------------------
__global__ void k_ring(const int* __restrict__ faces, int F) {
    int f = blockIdx.x * blockDim.x + threadIdx.x;
    if (f >= F) return;
    int a = faces[3 * f], b = faces[3 * f + 1], c = faces[3 * f + 2];
    int s;
    s = atomicAdd(&g_cnt[a], 1); g_ring[a * 6 + s] = make_int2(b, c);
    s = atomicAdd(&g_cnt[b], 1); g_ring[b * 6 + s] = make_int2(c, a);
    s = atomicAdd(&g_cnt[c], 1); g_ring[c * 6 + s] = make_int2(a, b);
}

// ---------------------------------------------------------------------------
// K2b: chain pairs into cyclic ring order, rotate to start at the minimal
// neighbor index (cyclic-invariant). deg-5: slot 5 duplicates slot 0 so its
// wrap cross term vanishes. cnt doubles as the vertex degree.
// ---------------------------------------------------------------------------
__global__ void k_order() {
    int v = blockIdx.x * blockDim.x + threadIdx.x;
    if (v >= NV) return;
    int cnt = g_cnt[v];
    int2 pr[6];
    #pragma unroll
    for (int i = 0; i < 6; i++)
        pr[i] = (i < cnt) ? g_ring[v * 6 + i] : make_int2(-1, -1);
    int ord[6];
    ord[0] = pr[0].x;
    int cur = pr[0].y;
    #pragma unroll
    for (int k = 1; k < 6; k++) {
        ord[k] = cur;
        int nxt = cur;
        #pragma unroll
        for (int i = 0; i < 6; i++)
            if (pr[i].x == cur) nxt = pr[i].y;
        cur = nxt;
    }
    int best = 0;
    #pragma unroll
    for (int i = 1; i < 6; i++)
        if (i < cnt && ord[i] < ord[best]) best = i;
    int rot[6];
    #pragma unroll
    for (int k = 0; k < 6; k++) {
        int idx = best + k;
        if (idx >= cnt) idx -= cnt;
        if (idx >= cnt) idx -= cnt;
        rot[k] = ord[idx];
    }
    if (cnt == 5) rot[5] = rot[0];
    g_nbr[2 * v]     = make_int4(rot[0], rot[1], rot[2], rot[3]);
    g_nbr[2 * v + 1] = make_int4(rot[4], rot[5], cnt, 0);
}

// ---------------------------------------------------------------------------
// K3: fused loss with shared-memory span tiling.
// The vertex numbering is raster grid order (5 stacked 128x256 blocks + 2
// poles), so interior ring neighbors lie within +-(XDIM+2) of the vertex
// index. Each block stages the contiguous span [v0-HALO, v0+TPB+HALO) with
// coalesced loads; neighbors inside the span come from smem, the few seam/
// pole cases fall back to __ldg. Correct for any topology.
// ---------------------------------------------------------------------------
__global__ void __launch_bounds__(TPB)
k_loss(const float* __restrict__ target, float* __restrict__ out,
       unsigned int nblocks) {
    __shared__ float4 sv[BPT][SPAN];   // 2*772*16 = 24704 B

    int v0  = blockIdx.x * TPB;
    int lo  = v0 - HALO;
    int b0  = blockIdx.y * BPT;

    // stage the span for all BPT batches (coalesced)
    for (int i = threadIdx.x; i < SPAN; i += TPB) {
        int g = lo + i;
        bool ok = (g >= 0) && (g < NV);
        #pragma unroll
        for (int bb = 0; bb < BPT; bb++) {
            sv[bb][i] = ok ? g_v4[(size_t)(b0 + bb) * NV + g]
                           : make_float4(0.f, 0.f, 0.f, 0.f);
        }
    }
    __syncthreads();

    int vtx = v0 + threadIdx.x;
    float local = 0.0f;
    if (vtx < NV) {
        int4 lo4 = g_nbr[2 * vtx];
        int4 hi4 = g_nbr[2 * vtx + 1];
        int n[6] = {lo4.x, lo4.y, lo4.z, lo4.w, hi4.x, hi4.y};
        int cnt  = hi4.z;
        // precompute span-local indices (or -1 for fallback)
        int li[6];
        #pragma unroll
        for (int i = 0; i < 6; i++) {
            int d = n[i] - lo;
            li[i] = ((unsigned)d < (unsigned)SPAN) ? d : -1;
        }
        int self = vtx - lo;   // always in span
        float invd = 1.0f / (float)cnt;
        const float inv3 = 1.0f / 3.0f;

        #pragma unroll
        for (int bb = 0; bb < BPT; bb++) {
            int b = b0 + bb;
            const float4* vb = g_v4 + (size_t)b * NV;

            float4 p[6];
            #pragma unroll
            for (int i = 0; i < 6; i++)
                p[i] = (li[i] >= 0) ? sv[bb][li[i]] : __ldg(vb + n[i]);
            float4 pv = sv[bb][self];

            // ring-ordered cross sum: vn = sum_j p_j x p_{(j+1)%6}
            float nx = 0.f, ny = 0.f, nz = 0.f;
            #pragma unroll
            for (int j = 0; j < 6; j++) {
                const float4 a = p[j];
                const float4 c = p[(j + 1) % 6];
                nx += a.y * c.z - a.z * c.y;
                ny += a.z * c.x - a.x * c.z;
                nz += a.x * c.y - a.y * c.x;
            }
            // neighbor sum (subtract the duplicated n0 if deg==5)
            float sx = 0.f, sy = 0.f, sz = 0.f;
            #pragma unroll
            for (int j = 0; j < 6; j++) { sx += p[j].x; sy += p[j].y; sz += p[j].z; }
            if (cnt == 5) { sx -= p[0].x; sy -= p[0].y; sz -= p[0].z; }

            const float* t = target + (size_t)b * 9 * NV + vtx;
            // position loss (streamed target reads: evict-first)
            float dx = pv.x - __ldcs(t);
            float dy = pv.y - __ldcs(t + (size_t)NV);
            float dz = pv.z - __ldcs(t + 2 * (size_t)NV);
            float lpos = dx * dx + dy * dy + dz * dz;
            // normal cosine loss
            float nn  = sqrtf(nx * nx + ny * ny + nz * nz);
            float inv = 1.0f / fmaxf(nn, 1e-12f);
            float ux = nx * inv, uy = ny * inv, uz = nz * inv;
            float un = sqrtf(ux * ux + uy * uy + uz * uz);
            float tx = __ldcs(t + 3 * (size_t)NV);
            float ty = __ldcs(t + 4 * (size_t)NV);
            float tz = __ldcs(t + 5 * (size_t)NV);
            float tn = sqrtf(tx * tx + ty * ty + tz * tz);
            float cosv = (ux * tx + uy * ty + uz * tz) / fmaxf(un * tn, 1e-8f);
            // Laplacian loss
            float dlx = (pv.x - sx * invd) - __ldcs(t + 6 * (size_t)NV);
            float dly = (pv.y - sy * invd) - __ldcs(t + 7 * (size_t)NV);
            float dlz = (pv.z - sz * invd) - __ldcs(t + 8 * (size_t)NV);
            float llap = dlx * dlx + dly * dly + dlz * dlz;

            local += (lpos + llap) * inv3 + (1.0f - cosv);
        }
    }

    // warp shuffle reduce, then cross-warp smem reduce, one atomic per block
    #pragma unroll
    for (int off = 16; off > 0; off >>= 1)
        local += __shfl_xor_sync(0xFFFFFFFFu, local, off);
    __shared__ float shw[TPB / 32];
    int wid = threadIdx.x >> 5;
    if ((threadIdx.x & 31) == 0) shw[wid] = local;
    __syncthreads();
    if (threadIdx.x == 0) {
        float s = 0.f;
        #pragma unroll
        for (int i = 0; i < TPB / 32; i++) s += shw[i];
        atomicAdd(&g_acc, (double)s);
        __threadfence();
        unsigned int ticket = atomicAdd(&g_done, 1u);
        if (ticket == nblocks - 1u) {
            out[0] = (float)(g_acc / ((double)BATCH * (double)NV));
        }
    }
}

extern "C" void kernel_launch(void* const* d_in, const int* in_sizes, int n_in,
                              void* d_out, int out_size) {
    const float* inputs = (const float*)d_in[0];
    const float* target = (const float*)d_in[1];
    const int*   faces  = (const int*)  d_in[2];
    int F = in_sizes[2] / 3;

    // Fork-join overlap: topology chain is independent of k_build_v.
    static cudaStream_t s_side = nullptr;
    static cudaEvent_t  s_fork = nullptr, s_join = nullptr;
    if (s_side == nullptr) {
        cudaStreamCreateWithFlags(&s_side, cudaStreamNonBlocking);
        cudaEventCreateWithFlags(&s_fork, cudaEventDisableTiming);
        cudaEventCreateWithFlags(&s_join, cudaEventDisableTiming);
    }
    cudaStream_t main_s = 0;

    dim3 blk256(256);

    // fork
    cudaEventRecord(s_fork, main_s);
    cudaStreamWaitEvent(s_side, s_fork, 0);

    // side stream: topology chain
    k_zero <<<(NV + 255) / 256, blk256, 0, s_side>>>();
    k_ring <<<(F + 255) / 256, blk256, 0, s_side>>>(faces, F);
    k_order<<<(NV + 255) / 256, blk256, 0, s_side>>>();
    cudaEventRecord(s_join, s_side);

    // main stream: vertex build, concurrent with the side chain
    k_build_v<<<dim3((YX + 2 + 255) / 256, BATCH), blk256, 0, main_s>>>(inputs);

    // join, then fused loss
    cudaStreamWaitEvent(main_s, s_join, 0);
    dim3 lgrid((NV + TPB - 1) / TPB, BATCH / BPT);
    unsigned int nblocks = lgrid.x * lgrid.y;
    k_loss<<<lgrid, TPB, 0, main_s>>>(target, (float*)d_out, nblocks);
}

// round 11
// speedup vs baseline: 1.2899x; 1.2899x over previous
#include <cuda_runtime.h>

// Problem constants (SUBDIVISIONS=7, BATCH=16)
#define BATCH 16
#define YDIM  640
#define XDIM  256
#define BH    128            // YDIM/5
#define YX    (YDIM*XDIM)    // 163840
#define NV    (YX + 2)       // 163842 vertices
#define BPT   4              // batches per thread in the fused loss kernel

// Scratch (static __device__ — no allocation allowed)
__device__ float4 g_v4[BATCH * NV];   // padded xyz_ per batch (~42 MB)
__device__ int    g_cnt[NV];          // per-vertex ring fill counters
__device__ int2   g_ring[NV * 6];     // per-vertex opposite-edge pairs (a,b)
__device__ double g_acc;              // fused loss accumulator
__device__ unsigned int g_done;       // ticket counter for fused finalization

// ---------------------------------------------------------------------------
// K1: build v = [grid verts ; top pole ; bottom pole] as float4 (w unused).
// inputs layout: (B, 3, Y, X) row-major
// ---------------------------------------------------------------------------
__global__ void k_build_v(const float* __restrict__ inp) {
    int vtx = blockIdx.x * blockDim.x + threadIdx.x;
    int b   = blockIdx.y;
    if (vtx > YX + 1) return;
    const float* base = inp + (size_t)b * 3 * YX;
    float4 o;
    o.w = 0.0f;
    if (vtx < YX) {
        o.x = base[vtx];
        o.y = base[YX + vtx];
        o.z = base[2 * YX + vtx];
    } else if (vtx == YX) {
        float s[3];
        #pragma unroll
        for (int c = 0; c < 3; c++) {
            s[c] = 0.0f;
            #pragma unroll
            for (int i = 0; i < 5; i++) s[c] += base[c * YX + (i * BH) * XDIM];
            s[c] *= 0.2f;
        }
        o.x = s[0]; o.y = s[1]; o.z = s[2];
    } else {
        float s[3];
        #pragma unroll
        for (int c = 0; c < 3; c++) {
            s[c] = 0.0f;
            #pragma unroll
            for (int i = 1; i <= 5; i++)
                s[c] += base[c * YX + (i * BH - 1) * XDIM + (XDIM - 1)];
            s[c] *= 0.2f;
        }
        o.x = s[0]; o.y = s[1]; o.z = s[2];
    }
    g_v4[(size_t)b * NV + vtx] = o;
}

// ---------------------------------------------------------------------------
// K2: collect per-vertex opposite-edge pairs from faces (batch-independent).
// Face (f0,f1,f2): pair (f1,f2)->f0, (f2,f0)->f1, (f0,f1)->f2.
// Identity: summing full face normals around a closed ring telescopes to
// vn[v] = sum_i a_i x b_i over opposite-edge pairs.
// Thread 0 also resets the loss accumulator and ticket (ordered before
// k_loss by the stream join).
// ---------------------------------------------------------------------------
__global__ void k_ring(const int* __restrict__ faces, int F) {
    int f = blockIdx.x * blockDim.x + threadIdx.x;
    if (f == 0) { g_acc = 0.0; g_done = 0u; }
    if (f >= F) return;
    int a = faces[3 * f], b = faces[3 * f + 1], c = faces[3 * f + 2];
    int s;
    s = atomicAdd(&g_cnt[a], 1); g_ring[a * 6 + s] = make_int2(b, c);
    s = atomicAdd(&g_cnt[b], 1); g_ring[b * 6 + s] = make_int2(c, a);
    s = atomicAdd(&g_cnt[c], 1); g_ring[c * 6 + s] = make_int2(a, b);
}

// ---------------------------------------------------------------------------
// K3: fused loss. One thread per vertex, BPT batches per thread.
// Chains the opposite-edge pairs into cyclic ring order in registers
// (succ(a)=b) and rotates to start at the minimal neighbor index — both
// absorbed into this latency-bound kernel's slack (validated in R4).
// vn = sum_j n_j x n_{j+1 mod 6}; for deg-5 slot 5 duplicates n_0 so the
// wrap cross term vanishes; cnt doubles as the vertex degree.
// Last block (ticket) writes the final scalar.
// ---------------------------------------------------------------------------
__global__ void __launch_bounds__(128)
k_loss(const float* __restrict__ target, float* __restrict__ out,
       unsigned int nblocks) {
    int vtx = blockIdx.x * blockDim.x + threadIdx.x;
    float local = 0.0f;
    if (vtx < NV) {
        int cnt = g_cnt[vtx];            // 5 or 6 == degree
        int2 pr[6];
        #pragma unroll
        for (int i = 0; i < 6; i++)
            pr[i] = (i < cnt) ? g_ring[vtx * 6 + i] : make_int2(-1, -1);
        // chain into cyclic order
        int ord[6];
        ord[0] = pr[0].x;
        int cur = pr[0].y;
        #pragma unroll
        for (int k = 1; k < 6; k++) {
            ord[k] = cur;
            int nxt = cur;
            #pragma unroll
            for (int i = 0; i < 6; i++)
                if (pr[i].x == cur) nxt = pr[i].y;
            cur = nxt;
        }
        // rotate to start at minimal neighbor index (cyclic-invariant,
        // improves warp gather coalescing)
        int best = 0;
        #pragma unroll
        for (int i = 1; i < 6; i++)
            if (i < cnt && ord[i] < ord[best]) best = i;
        int n[6];
        #pragma unroll
        for (int k = 0; k < 6; k++) {
            int idx = best + k;
            if (idx >= cnt) idx -= cnt;
            if (idx >= cnt) idx -= cnt;
            n[k] = ord[idx];
        }
        if (cnt == 5) n[5] = n[0];       // duplicated: wrap cross term = 0

        float invd = 1.0f / (float)cnt;
        const float inv3 = 1.0f / 3.0f;

        #pragma unroll
        for (int bb = 0; bb < BPT; bb++) {
            int b = blockIdx.y * BPT + bb;
            const float4* vb = g_v4 + (size_t)b * NV;

            float4 p[6];
            #pragma unroll
            for (int i = 0; i < 6; i++) p[i] = __ldg(vb + n[i]);
            float4 pv = __ldg(vb + vtx);

            // ring-ordered cross sum: vn = sum_j p_j x p_{(j+1)%6}
            float nx = 0.f, ny = 0.f, nz = 0.f;
            #pragma unroll
            for (int j = 0; j < 6; j++) {
                const float4 a = p[j];
                const float4 c = p[(j + 1) % 6];
                nx += a.y * c.z - a.z * c.y;
                ny += a.z * c.x - a.x * c.z;
                nz += a.x * c.y - a.y * c.x;
            }
            // neighbor sum (subtract the duplicated n0 if deg==5)
            float sx = 0.f, sy = 0.f, sz = 0.f;
            #pragma unroll
            for (int j = 0; j < 6; j++) { sx += p[j].x; sy += p[j].y; sz += p[j].z; }
            if (cnt == 5) { sx -= p[0].x; sy -= p[0].y; sz -= p[0].z; }

            const float* t = target + (size_t)b * 9 * NV + vtx;
            // position loss (streamed target reads: evict-first)
            float dx = pv.x - __ldcs(t);
            float dy = pv.y - __ldcs(t + (size_t)NV);
            float dz = pv.z - __ldcs(t + 2 * (size_t)NV);
            float lpos = dx * dx + dy * dy + dz * dz;
            // normal cosine loss
            float nn  = sqrtf(nx * nx + ny * ny + nz * nz);
            float inv = 1.0f / fmaxf(nn, 1e-12f);
            float ux = nx * inv, uy = ny * inv, uz = nz * inv;
            float un = sqrtf(ux * ux + uy * uy + uz * uz);
            float tx = __ldcs(t + 3 * (size_t)NV);
            float ty = __ldcs(t + 4 * (size_t)NV);
            float tz = __ldcs(t + 5 * (size_t)NV);
            float tn = sqrtf(tx * tx + ty * ty + tz * tz);
            float cosv = (ux * tx + uy * ty + uz * tz) / fmaxf(un * tn, 1e-8f);
            // Laplacian loss
            float dlx = (pv.x - sx * invd) - __ldcs(t + 6 * (size_t)NV);
            float dly = (pv.y - sy * invd) - __ldcs(t + 7 * (size_t)NV);
            float dlz = (pv.z - sz * invd) - __ldcs(t + 8 * (size_t)NV);
            float llap = dlx * dlx + dly * dly + dlz * dlz;

            local += (lpos + llap) * inv3 + (1.0f - cosv);
        }
    }

    // warp shuffle reduce, then cross-warp smem reduce, one atomic per block
    #pragma unroll
    for (int off = 16; off > 0; off >>= 1)
        local += __shfl_xor_sync(0xFFFFFFFFu, local, off);
    __shared__ float shw[4];
    int wid = threadIdx.x >> 5;
    if ((threadIdx.x & 31) == 0) shw[wid] = local;
    __syncthreads();
    if (threadIdx.x == 0) {
        float s = shw[0] + shw[1] + shw[2] + shw[3];
        atomicAdd(&g_acc, (double)s);
        __threadfence();
        unsigned int ticket = atomicAdd(&g_done, 1u);
        if (ticket == nblocks - 1u) {
            out[0] = (float)(g_acc / ((double)BATCH * (double)NV));
        }
    }
}

extern "C" void kernel_launch(void* const* d_in, const int* in_sizes, int n_in,
                              void* d_out, int out_size) {
    const float* inputs = (const float*)d_in[0];
    const float* target = (const float*)d_in[1];
    const int*   faces  = (const int*)  d_in[2];
    int F = in_sizes[2] / 3;

    // Fork-join overlap: the topology chain (memset g_cnt -> k_ring) is
    // data-independent of k_build_v and now shorter than it, so build_v
    // sets the pre-loss critical path. Stream/event/symbol-address setup
    // happens once on the eager correctness call; the captured graph reuses
    // the same dependency structure. cudaMemsetAsync is capture-legal.
    static cudaStream_t s_side = nullptr;
    static cudaEvent_t  s_fork = nullptr, s_join = nullptr;
    static void* s_cnt_ptr = nullptr;
    if (s_side == nullptr) {
        cudaStreamCreateWithFlags(&s_side, cudaStreamNonBlocking);
        cudaEventCreateWithFlags(&s_fork, cudaEventDisableTiming);
        cudaEventCreateWithFlags(&s_join, cudaEventDisableTiming);
        cudaGetSymbolAddress(&s_cnt_ptr, g_cnt);
    }
    cudaStream_t main_s = 0;

    dim3 blk256(256);

    // fork
    cudaEventRecord(s_fork, main_s);
    cudaStreamWaitEvent(s_side, s_fork, 0);

    // side stream: zero counters (memset node) then build the ring pairs
    cudaMemsetAsync(s_cnt_ptr, 0, NV * sizeof(int), s_side);
    k_ring<<<(F + 255) / 256, blk256, 0, s_side>>>(faces, F);
    cudaEventRecord(s_join, s_side);

    // main stream: vertex build, concurrent with the side chain
    k_build_v<<<dim3((YX + 2 + 255) / 256, BATCH), blk256, 0, main_s>>>(inputs);

    // join, then fused loss (chains + rotates rings inline)
    cudaStreamWaitEvent(main_s, s_join, 0);
    dim3 lgrid((NV + 127) / 128, BATCH / BPT);
    unsigned int nblocks = lgrid.x * lgrid.y;
    k_loss<<<lgrid, 128, 0, main_s>>>(target, (float*)d_out, nblocks);
}